// round 6
// baseline (speedup 1.0000x reference)
#include <cuda_runtime.h>
#include <math.h>

// Problem constants (from reference setup_inputs)
#define NB 4
#define NE 16
#define NP 320000          // 400*800
#define NQ 80000           // NP/4 pixel-quads
#define NC 20
#define CK 19              // kept classes (exclude IGNORE=0)

// k_accum: 40 tiles x 4 batches x 5 chunks (4 e-quads + 1 count), 128 thr
#define AT_TILE 8192
#define AQPT 16            // quads per thread = 8192/4/128
#define ATILES 40          // ceil(320000/8192)

// k_var: 256 thr, 2 quads per thread
#define VQPT 2
#define VTILES 157         // ceil(80000/512)
#define TOTAL_VBLK (VTILES * NB)

__device__ float g_sums[NB][NC][NE];
__device__ float g_counts[NB][NC];
__device__ float g_hinge[NB][NC];
__device__ unsigned int g_ticket;   // zero-init; last k_var block resets it

// Pass 1: per-class sums, 4 e-planes at a time with float4 shared columns
// (component = e-dim), 2-deep software pipeline on the global loads.
__global__ __launch_bounds__(128) void k_accum(const float* __restrict__ emb,
                                               const int* __restrict__ tgt) {
    __shared__ float4 s4[NC * 128];    // 40 KB
    const int tid = threadIdx.x;
    const int n = blockIdx.y;
    const int chunk = blockIdx.z;
    const int p0 = blockIdx.x * AT_TILE;
    const int w = tid >> 5;
    const int lane = tid & 31;
    const int* tl = tgt + (size_t)n * NP;

    if (chunk < 4) {
        const int e0 = chunk * 4;
        const float* pl0 = emb + ((size_t)(n * NE + e0 + 0)) * NP;
        const float* pl1 = emb + ((size_t)(n * NE + e0 + 1)) * NP;
        const float* pl2 = emb + ((size_t)(n * NE + e0 + 2)) * NP;
        const float* pl3 = emb + ((size_t)(n * NE + e0 + 3)) * NP;

#pragma unroll
        for (int c = 0; c < NC; c++)
            s4[c * 128 + tid] = make_float4(0.f, 0.f, 0.f, 0.f);
        // no sync: each thread touches only its own column until the reduce

        int4 lb[2];
        float4 va[2], vb[2], vc[2], vd[2];
        bool vld[2];

        {   // prologue: stage 0 = quad 0
            int p = p0 + tid * 4;
            vld[0] = (p < NP);
            if (vld[0]) {
                lb[0] = *(const int4*)(tl + p);
                va[0] = *(const float4*)(pl0 + p);
                vb[0] = *(const float4*)(pl1 + p);
                vc[0] = *(const float4*)(pl2 + p);
                vd[0] = *(const float4*)(pl3 + p);
            }
        }

#pragma unroll
        for (int q = 0; q < AQPT; q++) {
            const int cur = q & 1, nxt = cur ^ 1;
            if (q + 1 < AQPT) {     // prefetch next quad while we compute
                int p = p0 + ((q + 1) * 128 + tid) * 4;
                vld[nxt] = (p < NP);
                if (vld[nxt]) {
                    lb[nxt] = *(const int4*)(tl + p);
                    va[nxt] = *(const float4*)(pl0 + p);
                    vb[nxt] = *(const float4*)(pl1 + p);
                    vc[nxt] = *(const float4*)(pl2 + p);
                    vd[nxt] = *(const float4*)(pl3 + p);
                }
            }
            if (vld[cur]) {
                int4 l = lb[cur];
                float4 a = va[cur], b = vb[cur], c4 = vc[cur], d4 = vd[cur];
                {   // pixel 0
                    float4* s = &s4[l.x * 128 + tid];
                    float4 t = *s;
                    t.x += a.x; t.y += b.x; t.z += c4.x; t.w += d4.x;
                    *s = t;
                }
                {   // pixel 1
                    float4* s = &s4[l.y * 128 + tid];
                    float4 t = *s;
                    t.x += a.y; t.y += b.y; t.z += c4.y; t.w += d4.y;
                    *s = t;
                }
                {   // pixel 2
                    float4* s = &s4[l.z * 128 + tid];
                    float4 t = *s;
                    t.x += a.z; t.y += b.z; t.z += c4.z; t.w += d4.z;
                    *s = t;
                }
                {   // pixel 3
                    float4* s = &s4[l.w * 128 + tid];
                    float4 t = *s;
                    t.x += a.w; t.y += b.w; t.z += c4.w; t.w += d4.w;
                    *s = t;
                }
            }
        }
        __syncthreads();

        // Reduce: warp w handles classes w, w+4, ...
        for (int c = w; c < NC; c += 4) {
            float4 v0 = s4[c * 128 + lane];
            float4 v1 = s4[c * 128 + lane + 32];
            float4 v2 = s4[c * 128 + lane + 64];
            float4 v3 = s4[c * 128 + lane + 96];
            float4 v;
            v.x = (v0.x + v1.x) + (v2.x + v3.x);
            v.y = (v0.y + v1.y) + (v2.y + v3.y);
            v.z = (v0.z + v1.z) + (v2.z + v3.z);
            v.w = (v0.w + v1.w) + (v2.w + v3.w);
#pragma unroll
            for (int o = 16; o > 0; o >>= 1) {
                v.x += __shfl_down_sync(0xffffffffu, v.x, o);
                v.y += __shfl_down_sync(0xffffffffu, v.y, o);
                v.z += __shfl_down_sync(0xffffffffu, v.z, o);
                v.w += __shfl_down_sync(0xffffffffu, v.w, o);
            }
            if (lane == 0) {
                atomicAdd(&g_sums[n][c][e0 + 0], v.x);
                atomicAdd(&g_sums[n][c][e0 + 1], v.y);
                atomicAdd(&g_sums[n][c][e0 + 2], v.z);
                atomicAdd(&g_sums[n][c][e0 + 3], v.w);
            }
        }
    } else {
        // count chunk: scalar columns in the same shared buffer
        float* sc = (float*)s4;
#pragma unroll
        for (int c = 0; c < NC; c++) sc[c * 128 + tid] = 0.f;

#pragma unroll 4
        for (int q = 0; q < AQPT; q++) {
            int p = p0 + (q * 128 + tid) * 4;
            if (p < NP) {
                int4 l = *(const int4*)(tl + p);
                sc[l.x * 128 + tid] += 1.f;
                sc[l.y * 128 + tid] += 1.f;
                sc[l.z * 128 + tid] += 1.f;
                sc[l.w * 128 + tid] += 1.f;
            }
        }
        __syncthreads();

        for (int c = w; c < NC; c += 4) {
            float v = (sc[c * 128 + lane] + sc[c * 128 + lane + 32]) +
                      (sc[c * 128 + lane + 64] + sc[c * 128 + lane + 96]);
#pragma unroll
            for (int o = 16; o > 0; o >>= 1)
                v += __shfl_down_sync(0xffffffffu, v, o);
            if (lane == 0) atomicAdd(&g_counts[n][c], v);
        }
    }
}

// Pass 2: per-pixel pull hinge; last block (atomic ticket) runs the finalize.
__global__ __launch_bounds__(256) void k_var(const float* __restrict__ emb,
                                             const int* __restrict__ tgt,
                                             float* __restrict__ out) {
    __shared__ float s_meanT[NE * NC];   // [e][c]: conflict-free gathers
    __shared__ float s_h[NC * 256];      // reused as finalize staging
    __shared__ unsigned int s_last;
    const int tid = threadIdx.x;
    const int n = blockIdx.y;
    const int q0 = blockIdx.x * (256 * VQPT);

    for (int i = tid; i < NC * NE; i += 256) {
        int c = i >> 4;
        int e = i & 15;
        s_meanT[e * NC + c] = g_sums[n][c][e] / g_counts[n][c];
    }
#pragma unroll
    for (int c = 0; c < NC; c++) s_h[c * 256 + tid] = 0.f;
    __syncthreads();

    const int* tl = tgt + (size_t)n * NP;
    const float* eb = emb + (size_t)n * NE * NP;

#pragma unroll
    for (int qi = 0; qi < VQPT; qi++) {
        int q = q0 + qi * 256 + tid;
        if (q < NQ) {
            int p = q * 4;
            int4 l = *(const int4*)(tl + p);
            float dx = 0.f, dy = 0.f, dz = 0.f, dw = 0.f;
#pragma unroll
            for (int e = 0; e < NE; e++) {
                float4 v = *(const float4*)(eb + (size_t)e * NP + p);
                const float* mrow = &s_meanT[e * NC];
                float t;
                t = v.x - mrow[l.x]; dx = fmaf(t, t, dx);
                t = v.y - mrow[l.y]; dy = fmaf(t, t, dy);
                t = v.z - mrow[l.z]; dz = fmaf(t, t, dz);
                t = v.w - mrow[l.w]; dw = fmaf(t, t, dw);
            }
            if (l.x != 0) {
                float d = (dx > 0.f) ? sqrtf(dx) : 0.f;
                float h = fmaxf(d - 0.5f, 0.f);
                s_h[l.x * 256 + tid] += h * h;
            }
            if (l.y != 0) {
                float d = (dy > 0.f) ? sqrtf(dy) : 0.f;
                float h = fmaxf(d - 0.5f, 0.f);
                s_h[l.y * 256 + tid] += h * h;
            }
            if (l.z != 0) {
                float d = (dz > 0.f) ? sqrtf(dz) : 0.f;
                float h = fmaxf(d - 0.5f, 0.f);
                s_h[l.z * 256 + tid] += h * h;
            }
            if (l.w != 0) {
                float d = (dw > 0.f) ? sqrtf(dw) : 0.f;
                float h = fmaxf(d - 0.5f, 0.f);
                s_h[l.w * 256 + tid] += h * h;
            }
        }
    }
    __syncthreads();

    {
        const int w = tid >> 5;
        const int lane = tid & 31;
        for (int c = 1 + w; c < NC; c += 8) {
            float v = 0.f;
#pragma unroll
            for (int k = 0; k < 8; k++) v += s_h[c * 256 + lane + k * 32];
#pragma unroll
            for (int o = 16; o > 0; o >>= 1)
                v += __shfl_down_sync(0xffffffffu, v, o);
            if (lane == 0) atomicAdd(&g_hinge[n][c], v);
        }
    }
    __syncthreads();

    // ---- last-block-finalize ticket ----
    if (tid == 0) {
        __threadfence();
        unsigned int old = atomicAdd(&g_ticket, 1u);
        s_last = (old == TOTAL_VBLK - 1) ? 1u : 0u;
    }
    __syncthreads();
    if (s_last == 0) return;
    __threadfence();

    // ---- finalize (one block, 256 threads). Stage means in s_h. ----
    float* s_mean = s_h;                 // NB*NC*NE = 1280 floats
    float* s_cnt  = s_h + 1280;          // NB*NC = 80
    float* s_red  = s_h + 1280 + 80;     // 8 warps * 3

    for (int i = tid; i < NB * NC; i += 256)
        s_cnt[i] = (&g_counts[0][0])[i];
    for (int i = tid; i < NB * NC * NE; i += 256) {
        int nn = i / (NC * NE);
        int c = (i % (NC * NE)) >> 4;
        s_mean[i] = (&g_sums[0][0][0])[i] / (&g_counts[0][0])[nn * NC + c];
    }
    __syncthreads();

    float acc_v = 0.f, acc_d = 0.f, acc_r = 0.f;

    for (int i = tid; i < NB * CK; i += 256) {
        int nn = i / CK;
        int c = 1 + i % CK;
        acc_v += __ldcg(&g_hinge[nn][c]) / s_cnt[nn * NC + c];
    }
    for (int i = tid; i < NB * CK * CK; i += 256) {
        int nn = i / (CK * CK);
        int r = i % (CK * CK);
        int a = 1 + r / CK;
        int b = 1 + r % CK;
        if (a != b) {
            const float* ma = &s_mean[(nn * NC + a) * NE];
            const float* mb = &s_mean[(nn * NC + b) * NE];
            float d2 = 0.f;
#pragma unroll
            for (int e = 0; e < NE; e++) {
                float df = ma[e] - mb[e];
                d2 = fmaf(df, df, d2);
            }
            float d = (d2 > 0.f) ? sqrtf(d2) : 0.f;
            float h = fmaxf(3.0f - d, 0.f);   // 2*DELTA_DIST
            acc_d += h * h;
        }
    }
    for (int i = tid; i < NB * CK; i += 256) {
        int nn = i / CK;
        int c = 1 + i % CK;
        const float* m = &s_mean[(nn * NC + c) * NE];
        float d2 = 0.f;
#pragma unroll
        for (int e = 0; e < NE; e++) d2 = fmaf(m[e], m[e], d2);
        acc_r += (d2 > 0.f) ? sqrtf(d2) : 0.f;
    }

#pragma unroll
    for (int o = 16; o > 0; o >>= 1) {
        acc_v += __shfl_down_sync(0xffffffffu, acc_v, o);
        acc_d += __shfl_down_sync(0xffffffffu, acc_d, o);
        acc_r += __shfl_down_sync(0xffffffffu, acc_r, o);
    }
    const int w = tid >> 5;
    const int lane = tid & 31;
    if (lane == 0) {
        s_red[w * 3 + 0] = acc_v;
        s_red[w * 3 + 1] = acc_d;
        s_red[w * 3 + 2] = acc_r;
    }
    __syncthreads();

    // Re-zero global accumulators + ticket for the next launch/replay.
    {
        float* s = &g_sums[0][0][0];
        for (int j = tid; j < NB * NC * NE; j += 256) s[j] = 0.f;
        float* c = &g_counts[0][0];
        for (int j = tid; j < NB * NC; j += 256) c[j] = 0.f;
        float* h = &g_hinge[0][0];
        for (int j = tid; j < NB * NC; j += 256) h[j] = 0.f;
        if (tid == 0) g_ticket = 0u;
    }

    if (tid == 0) {
        float v = 0.f, d = 0.f, r = 0.f;
#pragma unroll
        for (int k = 0; k < 8; k++) {
            v += s_red[k * 3 + 0];
            d += s_red[k * 3 + 1];
            r += s_red[k * 3 + 2];
        }
        float tot = v / (float)CK
                  + d / (float)(CK * (CK - 1))
                  + 0.001f * (r / (float)CK);
        out[0] = tot * 0.25f;   // mean over batch
    }
}

extern "C" void kernel_launch(void* const* d_in, const int* in_sizes, int n_in,
                              void* d_out, int out_size) {
    const float* emb = (const float*)d_in[0];
    const int* tgt = (const int*)d_in[1];
    float* out = (float*)d_out;

    dim3 grid_a(ATILES, NB, 5);
    k_accum<<<grid_a, 128>>>(emb, tgt);
    dim3 grid_v(VTILES, NB);
    k_var<<<grid_v, 256>>>(emb, tgt, out);
}

// round 7
// speedup vs baseline: 1.0548x; 1.0548x over previous
#include <cuda_runtime.h>
#include <math.h>

// Problem constants (from reference setup_inputs)
#define NB 4
#define NE 16
#define NP 320000          // 400*800
#define NQ 80000           // NP/4 pixel-quads
#define NC 20
#define CK 19              // kept classes (exclude IGNORE=0)

// k_accum: 40 tiles x 4 batches x 5 chunks (4 e-quads + 1 count), 128 thr
#define AT_TILE 8192
#define AQPT 16            // quads per thread = 8192/4/128
#define ATILES 40          // ceil(320000/8192)

// k_var: 256 thr, 2 quads per thread
#define VQPT 2
#define VTILES 157         // ceil(80000/512)
#define TOTAL_VBLK (VTILES * NB)

__device__ float g_sums[NB][NC][NE];
__device__ float g_counts[NB][NC];
__device__ float g_varsum;          // sum over all pixels of hinge/count
__device__ unsigned int g_ticket;   // zero-init; last k_var block resets it

// Pass 1: per-class sums, 4 e-planes at a time with float4 shared columns
// (component = e-dim), 2-deep software pipeline on the global loads.
__global__ __launch_bounds__(128) void k_accum(const float* __restrict__ emb,
                                               const int* __restrict__ tgt) {
    __shared__ float4 s4[NC * 128];    // 40 KB
    const int tid = threadIdx.x;
    const int n = blockIdx.y;
    const int chunk = blockIdx.z;
    const int p0 = blockIdx.x * AT_TILE;
    const int w = tid >> 5;
    const int lane = tid & 31;
    const int* tl = tgt + (size_t)n * NP;

    if (chunk < 4) {
        const int e0 = chunk * 4;
        const float* pl0 = emb + ((size_t)(n * NE + e0 + 0)) * NP;
        const float* pl1 = emb + ((size_t)(n * NE + e0 + 1)) * NP;
        const float* pl2 = emb + ((size_t)(n * NE + e0 + 2)) * NP;
        const float* pl3 = emb + ((size_t)(n * NE + e0 + 3)) * NP;

#pragma unroll
        for (int c = 0; c < NC; c++)
            s4[c * 128 + tid] = make_float4(0.f, 0.f, 0.f, 0.f);
        // no sync: each thread touches only its own column until the reduce

        int4 lb[2];
        float4 va[2], vb[2], vc[2], vd[2];
        bool vld[2];

        {   // prologue
            int p = p0 + tid * 4;
            vld[0] = (p < NP);
            if (vld[0]) {
                lb[0] = *(const int4*)(tl + p);
                va[0] = *(const float4*)(pl0 + p);
                vb[0] = *(const float4*)(pl1 + p);
                vc[0] = *(const float4*)(pl2 + p);
                vd[0] = *(const float4*)(pl3 + p);
            }
        }

#pragma unroll
        for (int q = 0; q < AQPT; q++) {
            const int cur = q & 1, nxt = cur ^ 1;
            if (q + 1 < AQPT) {     // prefetch next quad while we compute
                int p = p0 + ((q + 1) * 128 + tid) * 4;
                vld[nxt] = (p < NP);
                if (vld[nxt]) {
                    lb[nxt] = *(const int4*)(tl + p);
                    va[nxt] = *(const float4*)(pl0 + p);
                    vb[nxt] = *(const float4*)(pl1 + p);
                    vc[nxt] = *(const float4*)(pl2 + p);
                    vd[nxt] = *(const float4*)(pl3 + p);
                }
            }
            if (vld[cur]) {
                int4 l = lb[cur];
                float4 a = va[cur], b = vb[cur], c4 = vc[cur], d4 = vd[cur];
                {
                    float4* s = &s4[l.x * 128 + tid];
                    float4 t = *s;
                    t.x += a.x; t.y += b.x; t.z += c4.x; t.w += d4.x;
                    *s = t;
                }
                {
                    float4* s = &s4[l.y * 128 + tid];
                    float4 t = *s;
                    t.x += a.y; t.y += b.y; t.z += c4.y; t.w += d4.y;
                    *s = t;
                }
                {
                    float4* s = &s4[l.z * 128 + tid];
                    float4 t = *s;
                    t.x += a.z; t.y += b.z; t.z += c4.z; t.w += d4.z;
                    *s = t;
                }
                {
                    float4* s = &s4[l.w * 128 + tid];
                    float4 t = *s;
                    t.x += a.w; t.y += b.w; t.z += c4.w; t.w += d4.w;
                    *s = t;
                }
            }
        }
        __syncthreads();

        for (int c = w; c < NC; c += 4) {
            float4 v0 = s4[c * 128 + lane];
            float4 v1 = s4[c * 128 + lane + 32];
            float4 v2 = s4[c * 128 + lane + 64];
            float4 v3 = s4[c * 128 + lane + 96];
            float4 v;
            v.x = (v0.x + v1.x) + (v2.x + v3.x);
            v.y = (v0.y + v1.y) + (v2.y + v3.y);
            v.z = (v0.z + v1.z) + (v2.z + v3.z);
            v.w = (v0.w + v1.w) + (v2.w + v3.w);
#pragma unroll
            for (int o = 16; o > 0; o >>= 1) {
                v.x += __shfl_down_sync(0xffffffffu, v.x, o);
                v.y += __shfl_down_sync(0xffffffffu, v.y, o);
                v.z += __shfl_down_sync(0xffffffffu, v.z, o);
                v.w += __shfl_down_sync(0xffffffffu, v.w, o);
            }
            if (lane == 0) {
                atomicAdd(&g_sums[n][c][e0 + 0], v.x);
                atomicAdd(&g_sums[n][c][e0 + 1], v.y);
                atomicAdd(&g_sums[n][c][e0 + 2], v.z);
                atomicAdd(&g_sums[n][c][e0 + 3], v.w);
            }
        }
    } else {
        float* sc = (float*)s4;
#pragma unroll
        for (int c = 0; c < NC; c++) sc[c * 128 + tid] = 0.f;

#pragma unroll 4
        for (int q = 0; q < AQPT; q++) {
            int p = p0 + (q * 128 + tid) * 4;
            if (p < NP) {
                int4 l = *(const int4*)(tl + p);
                sc[l.x * 128 + tid] += 1.f;
                sc[l.y * 128 + tid] += 1.f;
                sc[l.z * 128 + tid] += 1.f;
                sc[l.w * 128 + tid] += 1.f;
            }
        }
        __syncthreads();

        for (int c = w; c < NC; c += 4) {
            float v = (sc[c * 128 + lane] + sc[c * 128 + lane + 32]) +
                      (sc[c * 128 + lane + 64] + sc[c * 128 + lane + 96]);
#pragma unroll
            for (int o = 16; o > 0; o >>= 1)
                v += __shfl_down_sync(0xffffffffu, v, o);
            if (lane == 0) atomicAdd(&g_counts[n][c], v);
        }
    }
}

// Pass 2: per-pixel pull hinge, weighted by 1/count at the pixel ->
// single scalar accumulator per thread. No per-class smem bookkeeping.
// Last block (atomic ticket) runs the finalize.
__global__ __launch_bounds__(256) void k_var(const float* __restrict__ emb,
                                             const int* __restrict__ tgt,
                                             float* __restrict__ out) {
    __shared__ float s_meanT[NE * NC];   // [e][c]: conflict-free gathers
    __shared__ float s_rinv[NC];         // 1/count per class (0 for IGNORE)
    __shared__ float s_red[8];
    __shared__ float s_fin[NB * NC * NE + NB * NC + 24];  // finalize staging
    __shared__ unsigned int s_last;
    const int tid = threadIdx.x;
    const int n = blockIdx.y;
    const int q0 = blockIdx.x * (256 * VQPT);

    for (int i = tid; i < NC * NE; i += 256) {
        int c = i >> 4;
        int e = i & 15;
        s_meanT[e * NC + c] = g_sums[n][c][e] / g_counts[n][c];
    }
    if (tid < NC) s_rinv[tid] = (tid == 0) ? 0.f : 1.f / g_counts[n][tid];
    __syncthreads();

    const int* tl = tgt + (size_t)n * NP;
    const float* eb = emb + (size_t)n * NE * NP;

    float acc = 0.f;

#pragma unroll
    for (int qi = 0; qi < VQPT; qi++) {
        int q = q0 + qi * 256 + tid;
        if (q < NQ) {
            int p = q * 4;
            int4 l = *(const int4*)(tl + p);
            float dx = 0.f, dy = 0.f, dz = 0.f, dw = 0.f;
            // two batches of 8 planes: force 8 LDG.128 in flight each
#pragma unroll
            for (int h = 0; h < 2; h++) {
                float4 v[8];
#pragma unroll
                for (int e = 0; e < 8; e++)
                    v[e] = *(const float4*)(eb + (size_t)(h * 8 + e) * NP + p);
#pragma unroll
                for (int e = 0; e < 8; e++) {
                    const float* mrow = &s_meanT[(h * 8 + e) * NC];
                    float t;
                    t = v[e].x - mrow[l.x]; dx = fmaf(t, t, dx);
                    t = v[e].y - mrow[l.y]; dy = fmaf(t, t, dy);
                    t = v[e].z - mrow[l.z]; dz = fmaf(t, t, dz);
                    t = v[e].w - mrow[l.w]; dw = fmaf(t, t, dw);
                }
            }
            float hv;
            hv = fmaxf(((dx > 0.f) ? sqrtf(dx) : 0.f) - 0.5f, 0.f);
            acc = fmaf(hv * hv, s_rinv[l.x], acc);
            hv = fmaxf(((dy > 0.f) ? sqrtf(dy) : 0.f) - 0.5f, 0.f);
            acc = fmaf(hv * hv, s_rinv[l.y], acc);
            hv = fmaxf(((dz > 0.f) ? sqrtf(dz) : 0.f) - 0.5f, 0.f);
            acc = fmaf(hv * hv, s_rinv[l.z], acc);
            hv = fmaxf(((dw > 0.f) ? sqrtf(dw) : 0.f) - 0.5f, 0.f);
            acc = fmaf(hv * hv, s_rinv[l.w], acc);
        }
    }

    // block reduce single scalar
#pragma unroll
    for (int o = 16; o > 0; o >>= 1)
        acc += __shfl_down_sync(0xffffffffu, acc, o);
    const int w = tid >> 5;
    const int lane = tid & 31;
    if (lane == 0) s_red[w] = acc;
    __syncthreads();
    if (tid == 0) {
        float v = 0.f;
#pragma unroll
        for (int k = 0; k < 8; k++) v += s_red[k];
        atomicAdd(&g_varsum, v);
    }

    // ---- last-block-finalize ticket ----
    if (tid == 0) {
        __threadfence();
        unsigned int old = atomicAdd(&g_ticket, 1u);
        s_last = (old == TOTAL_VBLK - 1) ? 1u : 0u;
    }
    __syncthreads();
    if (s_last == 0) return;
    __threadfence();

    // ---- finalize (one block, 256 threads) ----
    float* s_mean = s_fin;                     // NB*NC*NE = 1280
    float* s_redf = s_fin + NB * NC * NE + NB * NC;

    for (int i = tid; i < NB * NC * NE; i += 256) {
        int nn = i / (NC * NE);
        int c = (i % (NC * NE)) >> 4;
        s_mean[i] = (&g_sums[0][0][0])[i] / (&g_counts[0][0])[nn * NC + c];
    }
    __syncthreads();

    float acc_d = 0.f, acc_r = 0.f;

    for (int i = tid; i < NB * CK * CK; i += 256) {
        int nn = i / (CK * CK);
        int r = i % (CK * CK);
        int a = 1 + r / CK;
        int b = 1 + r % CK;
        if (a != b) {
            const float* ma = &s_mean[(nn * NC + a) * NE];
            const float* mb = &s_mean[(nn * NC + b) * NE];
            float d2 = 0.f;
#pragma unroll
            for (int e = 0; e < NE; e++) {
                float df = ma[e] - mb[e];
                d2 = fmaf(df, df, d2);
            }
            float d = (d2 > 0.f) ? sqrtf(d2) : 0.f;
            float h = fmaxf(3.0f - d, 0.f);   // 2*DELTA_DIST
            acc_d += h * h;
        }
    }
    for (int i = tid; i < NB * CK; i += 256) {
        int nn = i / CK;
        int c = 1 + i % CK;
        const float* m = &s_mean[(nn * NC + c) * NE];
        float d2 = 0.f;
#pragma unroll
        for (int e = 0; e < NE; e++) d2 = fmaf(m[e], m[e], d2);
        acc_r += (d2 > 0.f) ? sqrtf(d2) : 0.f;
    }

#pragma unroll
    for (int o = 16; o > 0; o >>= 1) {
        acc_d += __shfl_down_sync(0xffffffffu, acc_d, o);
        acc_r += __shfl_down_sync(0xffffffffu, acc_r, o);
    }
    if (lane == 0) {
        s_redf[w * 2 + 0] = acc_d;
        s_redf[w * 2 + 1] = acc_r;
    }
    __syncthreads();

    // Re-zero global accumulators + ticket for the next launch/replay.
    {
        float* s = &g_sums[0][0][0];
        for (int j = tid; j < NB * NC * NE; j += 256) s[j] = 0.f;
        float* c = &g_counts[0][0];
        for (int j = tid; j < NB * NC; j += 256) c[j] = 0.f;
    }

    if (tid == 0) {
        float d = 0.f, r = 0.f;
#pragma unroll
        for (int k = 0; k < 8; k++) {
            d += s_redf[k * 2 + 0];
            r += s_redf[k * 2 + 1];
        }
        float v = __ldcg(&g_varsum);
        float tot = v / (float)CK
                  + d / (float)(CK * (CK - 1))
                  + 0.001f * (r / (float)CK);
        out[0] = tot * 0.25f;   // mean over batch
        g_varsum = 0.f;
        g_ticket = 0u;
    }
}

extern "C" void kernel_launch(void* const* d_in, const int* in_sizes, int n_in,
                              void* d_out, int out_size) {
    const float* emb = (const float*)d_in[0];
    const int* tgt = (const int*)d_in[1];
    float* out = (float*)d_out;

    dim3 grid_a(ATILES, NB, 5);
    k_accum<<<grid_a, 128>>>(emb, tgt);
    dim3 grid_v(VTILES, NB);
    k_var<<<grid_v, 256>>>(emb, tgt, out);
}

// round 8
// speedup vs baseline: 1.1079x; 1.0504x over previous
#include <cuda_runtime.h>
#include <math.h>

// Problem constants (from reference setup_inputs)
#define NB 4
#define NE 16
#define NP 320000          // 400*800
#define NQ 80000           // NP/4 pixel-quads
#define NC 20
#define CK 19              // kept classes (exclude IGNORE=0)

// k_accum: 40 tiles x 4 batches x 5 chunks (4 e-quads + 1 count), 128 thr
#define AT_TILE 8192
#define AQPT 16            // quads per thread = 8192/4/128
#define ATILES 40          // ceil(320000/8192)

// k_var: 256 thr, 2 quads per thread
#define VQPT 2
#define VTILES 157         // ceil(80000/512)
#define TOTAL_VBLK (VTILES * NB)

__device__ float g_sums[NB][NC][NE];
__device__ float g_counts[NB][NC];
__device__ float g_varsum;          // sum over all pixels of hinge/count
__device__ unsigned int g_ticket;   // zero-init; last k_var block resets it

// Pass 1: per-class sums, 4 e-planes at a time with float4 shared columns
// (component = e-dim), 2-deep software pipeline on the global loads.
__global__ __launch_bounds__(128) void k_accum(const float* __restrict__ emb,
                                               const int* __restrict__ tgt) {
    __shared__ float4 s4[NC * 128];    // 40 KB
    const int tid = threadIdx.x;
    const int n = blockIdx.y;
    const int chunk = blockIdx.z;
    const int p0 = blockIdx.x * AT_TILE;
    const int w = tid >> 5;
    const int lane = tid & 31;
    const int* tl = tgt + (size_t)n * NP;

    if (chunk < 4) {
        const int e0 = chunk * 4;
        const float* pl0 = emb + ((size_t)(n * NE + e0 + 0)) * NP;
        const float* pl1 = emb + ((size_t)(n * NE + e0 + 1)) * NP;
        const float* pl2 = emb + ((size_t)(n * NE + e0 + 2)) * NP;
        const float* pl3 = emb + ((size_t)(n * NE + e0 + 3)) * NP;

#pragma unroll
        for (int c = 0; c < NC; c++)
            s4[c * 128 + tid] = make_float4(0.f, 0.f, 0.f, 0.f);
        // no sync: each thread touches only its own column until the reduce

        int4 lb[2];
        float4 va[2], vb[2], vc[2], vd[2];
        bool vld[2];

        {   // prologue
            int p = p0 + tid * 4;
            vld[0] = (p < NP);
            if (vld[0]) {
                lb[0] = *(const int4*)(tl + p);
                va[0] = *(const float4*)(pl0 + p);
                vb[0] = *(const float4*)(pl1 + p);
                vc[0] = *(const float4*)(pl2 + p);
                vd[0] = *(const float4*)(pl3 + p);
            }
        }

#pragma unroll
        for (int q = 0; q < AQPT; q++) {
            const int cur = q & 1, nxt = cur ^ 1;
            if (q + 1 < AQPT) {     // prefetch next quad while we compute
                int p = p0 + ((q + 1) * 128 + tid) * 4;
                vld[nxt] = (p < NP);
                if (vld[nxt]) {
                    lb[nxt] = *(const int4*)(tl + p);
                    va[nxt] = *(const float4*)(pl0 + p);
                    vb[nxt] = *(const float4*)(pl1 + p);
                    vc[nxt] = *(const float4*)(pl2 + p);
                    vd[nxt] = *(const float4*)(pl3 + p);
                }
            }
            if (vld[cur]) {
                int4 l = lb[cur];
                float4 a = va[cur], b = vb[cur], c4 = vc[cur], d4 = vd[cur];
                {
                    float4* s = &s4[l.x * 128 + tid];
                    float4 t = *s;
                    t.x += a.x; t.y += b.x; t.z += c4.x; t.w += d4.x;
                    *s = t;
                }
                {
                    float4* s = &s4[l.y * 128 + tid];
                    float4 t = *s;
                    t.x += a.y; t.y += b.y; t.z += c4.y; t.w += d4.y;
                    *s = t;
                }
                {
                    float4* s = &s4[l.z * 128 + tid];
                    float4 t = *s;
                    t.x += a.z; t.y += b.z; t.z += c4.z; t.w += d4.z;
                    *s = t;
                }
                {
                    float4* s = &s4[l.w * 128 + tid];
                    float4 t = *s;
                    t.x += a.w; t.y += b.w; t.z += c4.w; t.w += d4.w;
                    *s = t;
                }
            }
        }
        __syncthreads();

        for (int c = w; c < NC; c += 4) {
            float4 v0 = s4[c * 128 + lane];
            float4 v1 = s4[c * 128 + lane + 32];
            float4 v2 = s4[c * 128 + lane + 64];
            float4 v3 = s4[c * 128 + lane + 96];
            float4 v;
            v.x = (v0.x + v1.x) + (v2.x + v3.x);
            v.y = (v0.y + v1.y) + (v2.y + v3.y);
            v.z = (v0.z + v1.z) + (v2.z + v3.z);
            v.w = (v0.w + v1.w) + (v2.w + v3.w);
#pragma unroll
            for (int o = 16; o > 0; o >>= 1) {
                v.x += __shfl_down_sync(0xffffffffu, v.x, o);
                v.y += __shfl_down_sync(0xffffffffu, v.y, o);
                v.z += __shfl_down_sync(0xffffffffu, v.z, o);
                v.w += __shfl_down_sync(0xffffffffu, v.w, o);
            }
            if (lane == 0) {
                atomicAdd(&g_sums[n][c][e0 + 0], v.x);
                atomicAdd(&g_sums[n][c][e0 + 1], v.y);
                atomicAdd(&g_sums[n][c][e0 + 2], v.z);
                atomicAdd(&g_sums[n][c][e0 + 3], v.w);
            }
        }
    } else {
        float* sc = (float*)s4;
#pragma unroll
        for (int c = 0; c < NC; c++) sc[c * 128 + tid] = 0.f;

#pragma unroll 4
        for (int q = 0; q < AQPT; q++) {
            int p = p0 + (q * 128 + tid) * 4;
            if (p < NP) {
                int4 l = *(const int4*)(tl + p);
                sc[l.x * 128 + tid] += 1.f;
                sc[l.y * 128 + tid] += 1.f;
                sc[l.z * 128 + tid] += 1.f;
                sc[l.w * 128 + tid] += 1.f;
            }
        }
        __syncthreads();

        for (int c = w; c < NC; c += 4) {
            float v = (sc[c * 128 + lane] + sc[c * 128 + lane + 32]) +
                      (sc[c * 128 + lane + 64] + sc[c * 128 + lane + 96]);
#pragma unroll
            for (int o = 16; o > 0; o >>= 1)
                v += __shfl_down_sync(0xffffffffu, v, o);
            if (lane == 0) atomicAdd(&g_counts[n][c], v);
        }
    }
}

// Pass 2: per-pixel pull hinge, weighted by 1/count at the pixel ->
// single scalar accumulator per thread. 4-plane register batches keep
// regs <= 51 so 5 CTAs/SM fit (62% occ). Last block runs the finalize.
__global__ __launch_bounds__(256, 5) void k_var(const float* __restrict__ emb,
                                                const int* __restrict__ tgt,
                                                float* __restrict__ out) {
    __shared__ float s_meanT[NE * NC];   // [e][c]: conflict-free gathers
    __shared__ float s_rinv[NC];         // 1/count per class (0 for IGNORE)
    __shared__ float s_red[8];
    __shared__ float s_fin[NB * NC * NE + NB * NC + 24];  // finalize staging
    __shared__ unsigned int s_last;
    const int tid = threadIdx.x;
    const int n = blockIdx.y;
    const int q0 = blockIdx.x * (256 * VQPT);

    for (int i = tid; i < NC * NE; i += 256) {
        int c = i >> 4;
        int e = i & 15;
        s_meanT[e * NC + c] = g_sums[n][c][e] / g_counts[n][c];
    }
    if (tid < NC) s_rinv[tid] = (tid == 0) ? 0.f : 1.f / g_counts[n][tid];
    __syncthreads();

    const int* tl = tgt + (size_t)n * NP;
    const float* eb = emb + (size_t)n * NE * NP;

    float acc = 0.f;

#pragma unroll
    for (int qi = 0; qi < VQPT; qi++) {
        int q = q0 + qi * 256 + tid;
        if (q < NQ) {
            int p = q * 4;
            int4 l = *(const int4*)(tl + p);
            float dx = 0.f, dy = 0.f, dz = 0.f, dw = 0.f;
            // four batches of 4 planes: 4 LDG.128 in flight, 16 regs of data
#pragma unroll
            for (int h = 0; h < 4; h++) {
                float4 v[4];
#pragma unroll
                for (int e = 0; e < 4; e++)
                    v[e] = *(const float4*)(eb + (size_t)(h * 4 + e) * NP + p);
#pragma unroll
                for (int e = 0; e < 4; e++) {
                    const float* mrow = &s_meanT[(h * 4 + e) * NC];
                    float t;
                    t = v[e].x - mrow[l.x]; dx = fmaf(t, t, dx);
                    t = v[e].y - mrow[l.y]; dy = fmaf(t, t, dy);
                    t = v[e].z - mrow[l.z]; dz = fmaf(t, t, dz);
                    t = v[e].w - mrow[l.w]; dw = fmaf(t, t, dw);
                }
            }
            float hv;
            hv = fmaxf(((dx > 0.f) ? sqrtf(dx) : 0.f) - 0.5f, 0.f);
            acc = fmaf(hv * hv, s_rinv[l.x], acc);
            hv = fmaxf(((dy > 0.f) ? sqrtf(dy) : 0.f) - 0.5f, 0.f);
            acc = fmaf(hv * hv, s_rinv[l.y], acc);
            hv = fmaxf(((dz > 0.f) ? sqrtf(dz) : 0.f) - 0.5f, 0.f);
            acc = fmaf(hv * hv, s_rinv[l.z], acc);
            hv = fmaxf(((dw > 0.f) ? sqrtf(dw) : 0.f) - 0.5f, 0.f);
            acc = fmaf(hv * hv, s_rinv[l.w], acc);
        }
    }

    // block reduce single scalar
#pragma unroll
    for (int o = 16; o > 0; o >>= 1)
        acc += __shfl_down_sync(0xffffffffu, acc, o);
    const int w = tid >> 5;
    const int lane = tid & 31;
    if (lane == 0) s_red[w] = acc;
    __syncthreads();
    if (tid == 0) {
        float v = 0.f;
#pragma unroll
        for (int k = 0; k < 8; k++) v += s_red[k];
        atomicAdd(&g_varsum, v);
    }

    // ---- last-block-finalize ticket ----
    if (tid == 0) {
        __threadfence();
        unsigned int old = atomicAdd(&g_ticket, 1u);
        s_last = (old == TOTAL_VBLK - 1) ? 1u : 0u;
    }
    __syncthreads();
    if (s_last == 0) return;
    __threadfence();

    // ---- finalize (one block, 256 threads) ----
    float* s_mean = s_fin;                     // NB*NC*NE = 1280
    float* s_redf = s_fin + NB * NC * NE + NB * NC;

    for (int i = tid; i < NB * NC * NE; i += 256) {
        int nn = i / (NC * NE);
        int c = (i % (NC * NE)) >> 4;
        s_mean[i] = (&g_sums[0][0][0])[i] / (&g_counts[0][0])[nn * NC + c];
    }
    __syncthreads();

    float acc_d = 0.f, acc_r = 0.f;

    for (int i = tid; i < NB * CK * CK; i += 256) {
        int nn = i / (CK * CK);
        int r = i % (CK * CK);
        int a = 1 + r / CK;
        int b = 1 + r % CK;
        if (a != b) {
            const float* ma = &s_mean[(nn * NC + a) * NE];
            const float* mb = &s_mean[(nn * NC + b) * NE];
            float d2 = 0.f;
#pragma unroll
            for (int e = 0; e < NE; e++) {
                float df = ma[e] - mb[e];
                d2 = fmaf(df, df, d2);
            }
            float d = (d2 > 0.f) ? sqrtf(d2) : 0.f;
            float h = fmaxf(3.0f - d, 0.f);   // 2*DELTA_DIST
            acc_d += h * h;
        }
    }
    for (int i = tid; i < NB * CK; i += 256) {
        int nn = i / CK;
        int c = 1 + i % CK;
        const float* m = &s_mean[(nn * NC + c) * NE];
        float d2 = 0.f;
#pragma unroll
        for (int e = 0; e < NE; e++) d2 = fmaf(m[e], m[e], d2);
        acc_r += (d2 > 0.f) ? sqrtf(d2) : 0.f;
    }

#pragma unroll
    for (int o = 16; o > 0; o >>= 1) {
        acc_d += __shfl_down_sync(0xffffffffu, acc_d, o);
        acc_r += __shfl_down_sync(0xffffffffu, acc_r, o);
    }
    if (lane == 0) {
        s_redf[w * 2 + 0] = acc_d;
        s_redf[w * 2 + 1] = acc_r;
    }
    __syncthreads();

    // Re-zero global accumulators + ticket for the next launch/replay.
    {
        float* s = &g_sums[0][0][0];
        for (int j = tid; j < NB * NC * NE; j += 256) s[j] = 0.f;
        float* c = &g_counts[0][0];
        for (int j = tid; j < NB * NC; j += 256) c[j] = 0.f;
    }

    if (tid == 0) {
        float d = 0.f, r = 0.f;
#pragma unroll
        for (int k = 0; k < 8; k++) {
            d += s_redf[k * 2 + 0];
            r += s_redf[k * 2 + 1];
        }
        float v = __ldcg(&g_varsum);
        float tot = v / (float)CK
                  + d / (float)(CK * (CK - 1))
                  + 0.001f * (r / (float)CK);
        out[0] = tot * 0.25f;   // mean over batch
        g_varsum = 0.f;
        g_ticket = 0u;
    }
}

extern "C" void kernel_launch(void* const* d_in, const int* in_sizes, int n_in,
                              void* d_out, int out_size) {
    const float* emb = (const float*)d_in[0];
    const int* tgt = (const int*)d_in[1];
    float* out = (float*)d_out;

    dim3 grid_a(ATILES, NB, 5);
    k_accum<<<grid_a, 128>>>(emb, tgt);
    dim3 grid_v(VTILES, NB);
    k_var<<<grid_v, 256>>>(emb, tgt, out);
}